// round 1
// baseline (speedup 1.0000x reference)
#include <cuda_runtime.h>
#include <cuda_bf16.h>
#include <math.h>

// Problem constants (fixed by the dataset)
#define MAXN 50048
#define MAXE 800000
#define INDIM 256
#define ODIM 128

// Scratch (device globals; no allocation allowed)
__device__ float g_h[(size_t)MAXN * ODIM];      // h_prime [N,128]
__device__ float g_edst[MAXN];                  // e_dst per node (incl bias)
__device__ float g_esrc[MAXN];                  // e_src per node (incl bias)
__device__ int   g_deg[MAXN];                   // in-degree per dst
__device__ int   g_row[MAXN + 1];               // CSR row offsets (exclusive scan)
__device__ int   g_cur[MAXN];                   // scatter cursors
__device__ int   g_elist[MAXE];                 // edge ids bucketed by dst

// ---------------------------------------------------------------------------
// 0: zero degree counters
// ---------------------------------------------------------------------------
__global__ void init_kernel(int n) {
    int i = blockIdx.x * blockDim.x + threadIdx.x;
    if (i < n) g_deg[i] = 0;
}

// ---------------------------------------------------------------------------
// 1: SGEMM h' = X @ W  (BM=64, BN=128=full, BK=16), fused e_dst/e_src logits
// 256 threads: tx = lane (0..31) covers 4 cols each, ty = warp (0..7) covers 8 rows
// ---------------------------------------------------------------------------
__global__ __launch_bounds__(256, 2)
void gemm_kernel(const float* __restrict__ A, const float* __restrict__ W,
                 const float* __restrict__ a_dst, const float* __restrict__ b_dst,
                 const float* __restrict__ a_src, const float* __restrict__ b_src,
                 int n) {
    __shared__ float As[16][64];
    __shared__ float Ws[16][128];

    const int tid = threadIdx.x;
    const int tx = tid & 31;     // lane: col group (4 cols)
    const int ty = tid >> 5;     // warp: row group (8 rows)
    const int block_row = blockIdx.x * 64;

    float acc[8][4];
#pragma unroll
    for (int i = 0; i < 8; i++)
#pragma unroll
        for (int j = 0; j < 4; j++) acc[i][j] = 0.f;

    for (int k0 = 0; k0 < INDIM; k0 += 16) {
        // Load A tile 64x16 (one float4 per thread), store transposed
        {
            int row = tid >> 2;
            int k4  = (tid & 3) * 4;
            int gr  = block_row + row;
            float4 v = make_float4(0.f, 0.f, 0.f, 0.f);
            if (gr < n) v = *(const float4*)(A + (size_t)gr * INDIM + k0 + k4);
            As[k4 + 0][row] = v.x;
            As[k4 + 1][row] = v.y;
            As[k4 + 2][row] = v.z;
            As[k4 + 3][row] = v.w;
        }
        // Load W tile 16x128 (two float4 per thread)
        {
            int idx = tid * 2;
#pragma unroll
            for (int t = 0; t < 2; t++) {
                int k  = (idx + t) >> 5;
                int c4 = ((idx + t) & 31) * 4;
                *(float4*)&Ws[k][c4] = *(const float4*)(W + (size_t)(k0 + k) * ODIM + c4);
            }
        }
        __syncthreads();

#pragma unroll
        for (int k = 0; k < 16; k++) {
            float4 a0 = *(float4*)&As[k][ty * 8];
            float4 a1 = *(float4*)&As[k][ty * 8 + 4];
            float4 w0 = *(float4*)&Ws[k][tx * 4];
            float ra[8] = {a0.x, a0.y, a0.z, a0.w, a1.x, a1.y, a1.z, a1.w};
#pragma unroll
            for (int i = 0; i < 8; i++) {
                acc[i][0] += ra[i] * w0.x;
                acc[i][1] += ra[i] * w0.y;
                acc[i][2] += ra[i] * w0.z;
                acc[i][3] += ra[i] * w0.w;
            }
        }
        __syncthreads();
    }

    // Epilogue: store h', fused e logits
    const float4 adv = *(const float4*)(a_dst + tx * 4);
    const float4 asv = *(const float4*)(a_src + tx * 4);
    const float bd = *b_dst;
    const float bs = *b_src;

#pragma unroll
    for (int i = 0; i < 8; i++) {
        int gr = block_row + ty * 8 + i;
        float pd = acc[i][0] * adv.x + acc[i][1] * adv.y + acc[i][2] * adv.z + acc[i][3] * adv.w;
        float ps = acc[i][0] * asv.x + acc[i][1] * asv.y + acc[i][2] * asv.z + acc[i][3] * asv.w;
#pragma unroll
        for (int o = 16; o; o >>= 1) {
            pd += __shfl_xor_sync(0xffffffffu, pd, o);
            ps += __shfl_xor_sync(0xffffffffu, ps, o);
        }
        if (gr < n) {
            *(float4*)(g_h + (size_t)gr * ODIM + tx * 4) =
                make_float4(acc[i][0], acc[i][1], acc[i][2], acc[i][3]);
            if (tx == 0) {
                g_edst[gr] = pd + bd;
                g_esrc[gr] = ps + bs;
            }
        }
    }
}

// ---------------------------------------------------------------------------
// 2: count in-degrees
// ---------------------------------------------------------------------------
__global__ void count_kernel(const int* __restrict__ edge_dst, int E) {
    int e = blockIdx.x * blockDim.x + threadIdx.x;
    if (e < E) atomicAdd(&g_deg[edge_dst[e]], 1);
}

// ---------------------------------------------------------------------------
// 3: single-block exclusive scan (8 elems/thread, 1024 threads -> 8192/chunk)
// ---------------------------------------------------------------------------
__global__ void scan_kernel(int n) {
    __shared__ int warp_sums[32];
    __shared__ int s_carry;
    const int tid  = threadIdx.x;
    const int lane = tid & 31;
    const int w    = tid >> 5;
    if (tid == 0) s_carry = 0;
    __syncthreads();

    const int CHUNK = 1024 * 8;
    for (int base = 0; base < n; base += CHUNK) {
        int v[8];
        int local = 0;
#pragma unroll
        for (int t = 0; t < 8; t++) {
            int i = base + tid * 8 + t;
            v[t] = (i < n) ? g_deg[i] : 0;
            local += v[t];
        }
        int incl = local;
#pragma unroll
        for (int o = 1; o < 32; o <<= 1) {
            int u = __shfl_up_sync(0xffffffffu, incl, o);
            if (lane >= o) incl += u;
        }
        if (lane == 31) warp_sums[w] = incl;
        __syncthreads();
        if (w == 0) {
            int s = warp_sums[lane];
#pragma unroll
            for (int o = 1; o < 32; o <<= 1) {
                int u = __shfl_up_sync(0xffffffffu, s, o);
                if (lane >= o) s += u;
            }
            warp_sums[lane] = s;
        }
        __syncthreads();
        int carry = s_carry;
        int excl = incl - local + (w > 0 ? warp_sums[w - 1] : 0) + carry;
        int run = excl;
#pragma unroll
        for (int t = 0; t < 8; t++) {
            int i = base + tid * 8 + t;
            if (i < n) { g_row[i] = run; g_cur[i] = run; }
            run += v[t];
        }
        int total = warp_sums[31];
        __syncthreads();
        if (tid == 0) s_carry = carry + total;
        __syncthreads();
    }
    if (tid == 0) g_row[n] = s_carry;
}

// ---------------------------------------------------------------------------
// 4: bucket edges by destination
// ---------------------------------------------------------------------------
__global__ void scatter_kernel(const int* __restrict__ edge_dst, int E) {
    int e = blockIdx.x * blockDim.x + threadIdx.x;
    if (e < E) {
        int d = edge_dst[e];
        int p = atomicAdd(&g_cur[d], 1);
        g_elist[p] = e;
    }
}

// ---------------------------------------------------------------------------
// 5: per-dst softmax + weighted aggregation, one warp per destination node
// ---------------------------------------------------------------------------
__global__ __launch_bounds__(256)
void agg_kernel(const int* __restrict__ edge_src,
                const float* __restrict__ out_bias,
                float* __restrict__ out, int n) {
    const int gw   = (blockIdx.x * blockDim.x + threadIdx.x) >> 5;
    const int lane = threadIdx.x & 31;
    if (gw >= n) return;

    const int beg = g_row[gw];
    const int end = g_row[gw + 1];
    const float ed = g_edst[gw];

    // pass 1: max score
    float m = -INFINITY;
    for (int i = beg + lane; i < end; i += 32) {
        int s = edge_src[g_elist[i]];
        float sc = ed + g_esrc[s];
        sc = sc >= 0.f ? sc : 0.2f * sc;
        m = fmaxf(m, sc);
    }
#pragma unroll
    for (int o = 16; o; o >>= 1) m = fmaxf(m, __shfl_xor_sync(0xffffffffu, m, o));

    // pass 2: sum of exp
    float sum = 0.f;
    for (int i = beg + lane; i < end; i += 32) {
        int s = edge_src[g_elist[i]];
        float sc = ed + g_esrc[s];
        sc = sc >= 0.f ? sc : 0.2f * sc;
        sum += __expf(sc - m);
    }
#pragma unroll
    for (int o = 16; o; o >>= 1) sum += __shfl_xor_sync(0xffffffffu, sum, o);
    const float inv = 1.f / fmaxf(sum, 1e-12f);

    // pass 3: weighted accumulate; whole warp cooperates per edge (512B gather)
    const int c = lane * 4;
    float a0 = 0.f, a1 = 0.f, a2 = 0.f, a3 = 0.f;
    for (int i = beg; i < end; i++) {
        int s = edge_src[g_elist[i]];
        float sc = ed + g_esrc[s];
        sc = sc >= 0.f ? sc : 0.2f * sc;
        float al = __expf(sc - m) * inv;
        float4 v = *(const float4*)(g_h + (size_t)s * ODIM + c);
        a0 += al * v.x; a1 += al * v.y; a2 += al * v.z; a3 += al * v.w;
    }

    float4 b4 = *(const float4*)(out_bias + c);
    a0 += b4.x; a1 += b4.y; a2 += b4.z; a3 += b4.w;
    float4 o4;
    o4.x = a0 > 0.f ? a0 : expm1f(a0);
    o4.y = a1 > 0.f ? a1 : expm1f(a1);
    o4.z = a2 > 0.f ? a2 : expm1f(a2);
    o4.w = a3 > 0.f ? a3 : expm1f(a3);
    *(float4*)(out + (size_t)gw * ODIM + c) = o4;
}

// ---------------------------------------------------------------------------
extern "C" void kernel_launch(void* const* d_in, const int* in_sizes, int n_in,
                              void* d_out, int out_size) {
    const float* inputs   = (const float*)d_in[0];
    const int*   edge_src = (const int*)d_in[1];
    const int*   edge_dst = (const int*)d_in[2];
    const float* W_seq    = (const float*)d_in[3];
    const float* a_dst    = (const float*)d_in[4];
    const float* b_dst    = (const float*)d_in[5];
    const float* a_src    = (const float*)d_in[6];
    const float* b_src    = (const float*)d_in[7];
    const float* out_bias = (const float*)d_in[8];
    float* out = (float*)d_out;

    const int n = in_sizes[0] / INDIM;
    const int E = in_sizes[1];

    init_kernel<<<(n + 255) / 256, 256>>>(n);
    gemm_kernel<<<(n + 63) / 64, 256>>>(inputs, W_seq, a_dst, b_dst, a_src, b_src, n);
    count_kernel<<<(E + 255) / 256, 256>>>(edge_dst, E);
    scan_kernel<<<1, 1024>>>(n);
    scatter_kernel<<<(E + 255) / 256, 256>>>(edge_dst, E);
    agg_kernel<<<(n * 32 + 255) / 256, 256>>>(edge_src, out_bias, out, n);
}

// round 3
// speedup vs baseline: 1.3648x; 1.3648x over previous
#include <cuda_runtime.h>
#include <cuda_bf16.h>
#include <math.h>

// Problem constants (fixed by the dataset)
#define MAXN 50048
#define MAXE 800000
#define INDIM 256
#define ODIM 128
#define SCAN_B 256
#define MAXB ((MAXN + SCAN_B - 1) / SCAN_B)

// Scratch (device globals; no allocation allowed)
__device__ float g_h[(size_t)MAXN * ODIM];      // h_prime [N,128]
__device__ float g_edst[MAXN];                  // e_dst per node (incl bias)
__device__ float g_esrc[MAXN];                  // e_src per node (incl bias)
__device__ int   g_deg[MAXN];                   // in-degree per dst
__device__ int   g_row[MAXN + 1];               // CSR row offsets
__device__ int   g_cur[MAXN];                   // scatter cursors
__device__ int   g_srcl[MAXE];                  // src node per bucketed edge
__device__ float g_score[MAXE];                 // leaky-relu score per bucketed edge
__device__ int   g_bsum[MAXB];                  // per-block degree sums
__device__ int   g_bscan[MAXB];                 // exclusive scan of block sums

// ---------------------------------------------------------------------------
// 0: zero degree counters
// ---------------------------------------------------------------------------
__global__ void init_kernel(int n) {
    int i = blockIdx.x * blockDim.x + threadIdx.x;
    if (i < n) g_deg[i] = 0;
}

// ---------------------------------------------------------------------------
// 1: SGEMM h' = X @ W  (BM=64, BN=128=full, BK=16), fused e_dst/e_src logits
// ---------------------------------------------------------------------------
__global__ __launch_bounds__(256, 2)
void gemm_kernel(const float* __restrict__ A, const float* __restrict__ W,
                 const float* __restrict__ a_dst, const float* __restrict__ b_dst,
                 const float* __restrict__ a_src, const float* __restrict__ b_src,
                 int n) {
    __shared__ float As[16][64];
    __shared__ float Ws[16][128];

    const int tid = threadIdx.x;
    const int tx = tid & 31;     // lane: col group (4 cols)
    const int ty = tid >> 5;     // warp: row group (8 rows)
    const int block_row = blockIdx.x * 64;

    float acc[8][4];
#pragma unroll
    for (int i = 0; i < 8; i++)
#pragma unroll
        for (int j = 0; j < 4; j++) acc[i][j] = 0.f;

    for (int k0 = 0; k0 < INDIM; k0 += 16) {
        {
            int row = tid >> 2;
            int k4  = (tid & 3) * 4;
            int gr  = block_row + row;
            float4 v = make_float4(0.f, 0.f, 0.f, 0.f);
            if (gr < n) v = *(const float4*)(A + (size_t)gr * INDIM + k0 + k4);
            As[k4 + 0][row] = v.x;
            As[k4 + 1][row] = v.y;
            As[k4 + 2][row] = v.z;
            As[k4 + 3][row] = v.w;
        }
        {
            int idx = tid * 2;
#pragma unroll
            for (int t = 0; t < 2; t++) {
                int k  = (idx + t) >> 5;
                int c4 = ((idx + t) & 31) * 4;
                *(float4*)&Ws[k][c4] = *(const float4*)(W + (size_t)(k0 + k) * ODIM + c4);
            }
        }
        __syncthreads();

#pragma unroll
        for (int k = 0; k < 16; k++) {
            float4 a0 = *(float4*)&As[k][ty * 8];
            float4 a1 = *(float4*)&As[k][ty * 8 + 4];
            float4 w0 = *(float4*)&Ws[k][tx * 4];
            float ra[8] = {a0.x, a0.y, a0.z, a0.w, a1.x, a1.y, a1.z, a1.w};
#pragma unroll
            for (int i = 0; i < 8; i++) {
                acc[i][0] += ra[i] * w0.x;
                acc[i][1] += ra[i] * w0.y;
                acc[i][2] += ra[i] * w0.z;
                acc[i][3] += ra[i] * w0.w;
            }
        }
        __syncthreads();
    }

    const float4 adv = *(const float4*)(a_dst + tx * 4);
    const float4 asv = *(const float4*)(a_src + tx * 4);
    const float bd = *b_dst;
    const float bs = *b_src;

#pragma unroll
    for (int i = 0; i < 8; i++) {
        int gr = block_row + ty * 8 + i;
        float pd = acc[i][0] * adv.x + acc[i][1] * adv.y + acc[i][2] * adv.z + acc[i][3] * adv.w;
        float ps = acc[i][0] * asv.x + acc[i][1] * asv.y + acc[i][2] * asv.z + acc[i][3] * asv.w;
#pragma unroll
        for (int o = 16; o; o >>= 1) {
            pd += __shfl_xor_sync(0xffffffffu, pd, o);
            ps += __shfl_xor_sync(0xffffffffu, ps, o);
        }
        if (gr < n) {
            *(float4*)(g_h + (size_t)gr * ODIM + tx * 4) =
                make_float4(acc[i][0], acc[i][1], acc[i][2], acc[i][3]);
            if (tx == 0) {
                g_edst[gr] = pd + bd;
                g_esrc[gr] = ps + bs;
            }
        }
    }
}

// ---------------------------------------------------------------------------
// 2: count in-degrees
// ---------------------------------------------------------------------------
__global__ void count_kernel(const int* __restrict__ edge_dst, int E) {
    int e = blockIdx.x * blockDim.x + threadIdx.x;
    if (e < E) atomicAdd(&g_deg[edge_dst[e]], 1);
}

// ---------------------------------------------------------------------------
// 3a: per-block local exclusive scan of g_deg -> g_row (partial), block sums
// ---------------------------------------------------------------------------
__global__ __launch_bounds__(SCAN_B)
void scanA_kernel(int n) {
    __shared__ int wsum[8];
    const int tid  = threadIdx.x;
    const int lane = tid & 31;
    const int w    = tid >> 5;
    const int i    = blockIdx.x * SCAN_B + tid;

    int v = (i < n) ? g_deg[i] : 0;
    int incl = v;
#pragma unroll
    for (int o = 1; o < 32; o <<= 1) {
        int u = __shfl_up_sync(0xffffffffu, incl, o);
        if (lane >= o) incl += u;
    }
    if (lane == 31) wsum[w] = incl;
    __syncthreads();
    if (w == 0 && lane < 8) {
        int s = wsum[lane];
#pragma unroll
        for (int o = 1; o < 8; o <<= 1) {
            int u = __shfl_up_sync(0x000000ffu, s, o);
            if (lane >= o) s += u;
        }
        wsum[lane] = s;
    }
    __syncthreads();
    int excl = incl - v + (w > 0 ? wsum[w - 1] : 0);
    if (i < n) g_row[i] = excl;
    if (tid == 0) g_bsum[blockIdx.x] = wsum[7];
}

// ---------------------------------------------------------------------------
// 3b: single-block exclusive scan of block sums
// ---------------------------------------------------------------------------
__global__ __launch_bounds__(SCAN_B)
void scanB_kernel(int nb, int n) {
    __shared__ int wsum[8];
    const int tid  = threadIdx.x;
    const int lane = tid & 31;
    const int w    = tid >> 5;

    int v = (tid < nb) ? g_bsum[tid] : 0;
    int incl = v;
#pragma unroll
    for (int o = 1; o < 32; o <<= 1) {
        int u = __shfl_up_sync(0xffffffffu, incl, o);
        if (lane >= o) incl += u;
    }
    if (lane == 31) wsum[w] = incl;
    __syncthreads();
    if (w == 0 && lane < 8) {
        int s = wsum[lane];
#pragma unroll
        for (int o = 1; o < 8; o <<= 1) {
            int u = __shfl_up_sync(0x000000ffu, s, o);
            if (lane >= o) s += u;
        }
        wsum[lane] = s;
    }
    __syncthreads();
    int excl = incl - v + (w > 0 ? wsum[w - 1] : 0);
    if (tid < nb) g_bscan[tid] = excl;
    if (tid == 0) g_row[n] = wsum[7];
}

// ---------------------------------------------------------------------------
// 3c: add block offsets, init cursors
// ---------------------------------------------------------------------------
__global__ __launch_bounds__(SCAN_B)
void scanC_kernel(int n) {
    const int i = blockIdx.x * SCAN_B + threadIdx.x;
    if (i < n) {
        int r = g_row[i] + g_bscan[blockIdx.x];
        g_row[i] = r;
        g_cur[i] = r;
    }
}

// ---------------------------------------------------------------------------
// 4: bucket edges by destination; materialize src index + leaky-relu score
// ---------------------------------------------------------------------------
__global__ void scatter_kernel(const int* __restrict__ edge_src,
                               const int* __restrict__ edge_dst, int E) {
    int e = blockIdx.x * blockDim.x + threadIdx.x;
    if (e < E) {
        int d = edge_dst[e];
        int s = edge_src[e];
        float sc = g_edst[d] + g_esrc[s];
        sc = sc >= 0.f ? sc : 0.2f * sc;
        int p = atomicAdd(&g_cur[d], 1);
        g_srcl[p]  = s;
        g_score[p] = sc;
    }
}

// ---------------------------------------------------------------------------
// 5: per-dst online softmax + weighted aggregation, one warp per dst node
// ---------------------------------------------------------------------------
__global__ __launch_bounds__(256)
void agg_kernel(const float* __restrict__ out_bias,
                float* __restrict__ out, int n) {
    const int gw   = (blockIdx.x * blockDim.x + threadIdx.x) >> 5;
    const int lane = threadIdx.x & 31;
    if (gw >= n) return;

    const int beg = g_row[gw];
    const int end = g_row[gw + 1];

    // single pass: online max + rescaled exp-sum (contiguous reads)
    float m = -INFINITY, ssum = 0.f;
    for (int i = beg + lane; i < end; i += 32) {
        float sc = g_score[i];
        if (sc > m) {
            ssum = ssum * __expf(m - sc) + 1.f;   // first iter: ssum==0, exp finite ignored
            m = sc;
        } else {
            ssum += __expf(sc - m);
        }
    }
    // warp combine: global max, then rescale partial sums
    float M = m;
#pragma unroll
    for (int o = 16; o; o >>= 1) M = fmaxf(M, __shfl_xor_sync(0xffffffffu, M, o));
    float part = (m == -INFINITY) ? 0.f : ssum * __expf(m - M);
#pragma unroll
    for (int o = 16; o; o >>= 1) part += __shfl_xor_sync(0xffffffffu, part, o);
    const float inv = 1.f / fmaxf(part, 1e-12f);

    // weighted accumulate; whole warp cooperates per edge (512B gather)
    const int c = lane * 4;
    float a0 = 0.f, a1 = 0.f, a2 = 0.f, a3 = 0.f;
    for (int i = beg; i < end; i++) {
        int s = g_srcl[i];
        float al = __expf(g_score[i] - M) * inv;
        float4 v = *(const float4*)(g_h + (size_t)s * ODIM + c);
        a0 += al * v.x; a1 += al * v.y; a2 += al * v.z; a3 += al * v.w;
    }

    float4 b4 = *(const float4*)(out_bias + c);
    a0 += b4.x; a1 += b4.y; a2 += b4.z; a3 += b4.w;
    float4 o4;
    o4.x = a0 > 0.f ? a0 : expm1f(a0);
    o4.y = a1 > 0.f ? a1 : expm1f(a1);
    o4.z = a2 > 0.f ? a2 : expm1f(a2);
    o4.w = a3 > 0.f ? a3 : expm1f(a3);
    *(float4*)(out + (size_t)gw * ODIM + c) = o4;
}

// ---------------------------------------------------------------------------
extern "C" void kernel_launch(void* const* d_in, const int* in_sizes, int n_in,
                              void* d_out, int out_size) {
    const float* inputs   = (const float*)d_in[0];
    const int*   edge_src = (const int*)d_in[1];
    const int*   edge_dst = (const int*)d_in[2];
    const float* W_seq    = (const float*)d_in[3];
    const float* a_dst    = (const float*)d_in[4];
    const float* b_dst    = (const float*)d_in[5];
    const float* a_src    = (const float*)d_in[6];
    const float* b_src    = (const float*)d_in[7];
    const float* out_bias = (const float*)d_in[8];
    float* out = (float*)d_out;

    const int n = in_sizes[0] / INDIM;
    const int E = in_sizes[1];
    const int nb = (n + SCAN_B - 1) / SCAN_B;

    init_kernel<<<(n + 255) / 256, 256>>>(n);
    gemm_kernel<<<(n + 63) / 64, 256>>>(inputs, W_seq, a_dst, b_dst, a_src, b_src, n);
    count_kernel<<<(E + 255) / 256, 256>>>(edge_dst, E);
    scanA_kernel<<<nb, SCAN_B>>>(n);
    scanB_kernel<<<1, SCAN_B>>>(nb, n);
    scanC_kernel<<<nb, SCAN_B>>>(n);
    scatter_kernel<<<(E + 255) / 256, 256>>>(edge_src, edge_dst, E);
    agg_kernel<<<(n * 32 + 255) / 256, 256>>>(out_bias, out, n);
}